// round 16
// baseline (speedup 1.0000x reference)
#include <cuda_runtime.h>
#include <math.h>

typedef unsigned long long ull;
#define Tn 96
#define Bn 64

__device__ __forceinline__ ull pk2(float lo, float hi) {
    ull r; asm("mov.b64 %0,{%1,%2};" : "=l"(r) : "f"(lo), "f"(hi)); return r;
}
__device__ __forceinline__ void upk2(ull v, float &a, float &b) {
    asm("mov.b64 {%0,%1},%2;" : "=f"(a), "=f"(b) : "l"(v));
}
__device__ __forceinline__ void ffma2(ull &d, ull a, ull b) {
    asm("fma.rn.f32x2 %0,%1,%2,%0;" : "+l"(d) : "l"(a), "l"(b));
}
__device__ __forceinline__ float sigm(float x) { return 1.f / (1.f + __expf(-x)); }
__device__ __forceinline__ float tanhfast(float x) {
    float t = __expf(-2.f * fabsf(x));
    return copysignf((1.f - t) / (1.f + t), x);
}
__device__ __forceinline__ unsigned s2u(const void* p) {
    unsigned a;
    asm("{ .reg .u64 t; cvta.to.shared.u64 t, %1; cvt.u32.u64 %0, t; }" : "=r"(a) : "l"(p));
    return a;
}
__device__ __forceinline__ unsigned mapa_rank(unsigned a, unsigned rank) {
    unsigned r; asm("mapa.shared::cluster.u32 %0, %1, %2;" : "=r"(r) : "r"(a), "r"(rank));
    return r;
}
__device__ __forceinline__ void st_rem_v4(unsigned a, float4 v) {
    asm volatile("st.shared::cluster.v4.f32 [%0], {%1,%2,%3,%4};"
                 :: "r"(a), "f"(v.x), "f"(v.y), "f"(v.z), "f"(v.w) : "memory");
}
__device__ __forceinline__ void flag_release(int* p) {
    asm volatile("red.release.gpu.global.add.s32 [%0], 1;" :: "l"(p) : "memory");
}
__device__ __forceinline__ int flag_acq(const int* p) {
    int v; asm volatile("ld.acquire.gpu.global.s32 %0, [%1];" : "=r"(v) : "l"(p) : "memory");
    return v;
}
#define CLUSTER_SYNC() do { \
    asm volatile("barrier.cluster.arrive.aligned;" ::: "memory"); \
    asm volatile("barrier.cluster.wait.aligned;" ::: "memory"); \
} while (0)

// ---------- device-global scratch ----------
__device__ __align__(256) float g_Pt[4 * 4096];                   // [m][k][n] = P_{m+1}[n][k]
__device__ __align__(256) float g_WX[2][5 * 64 * 192];
__device__ __align__(256) float g_WgH[2][5 * 64 * 128];
__device__ __align__(256) float g_WcH[2][5 * 64 * 64];
__device__ __align__(256) float g_Gx[(size_t)Tn * Bn * 64 * 128];
__device__ __align__(256) float g_Cx[(size_t)Tn * Bn * 64 * 64];
__device__ __align__(256) float g_Hseq[(size_t)Tn * Bn * 4096];
__device__ __align__(256) float g_Last[Bn * 4096];
__device__ __align__(256) int   g_prog[128];                      // [b][hf] recur0 step progress
__device__ __align__(256) int   g_prog1[Tn * Bn];                 // pre1 per-(t,b) done flags

// ---------- P matrices ----------
__global__ void k_prep(const float* __restrict__ S0, const float* __restrict__ S1) {
    __shared__ float s0[4096], s1[4096];
    int tid = threadIdx.x;
    if (tid < 128) g_prog[tid] = 0;
    for (int i = tid; i < Tn * Bn; i += 256) g_prog1[i] = 0;
    for (int i = tid; i < 4096; i += 256) { s0[i] = S0[i]; s1[i] = S1[i]; }
    __syncthreads();
    for (int i = tid; i < 4096; i += 256) {
        int n = i >> 6, k = i & 63;
        float a2 = 0.f, a3 = 0.f;
        for (int j = 0; j < 64; j++) {
            a2 += s0[n * 64 + j] * s0[j * 64 + k];
            a3 += s1[n * 64 + j] * s0[j * 64 + k];
        }
        g_Pt[k * 64 + n] = s0[i];
        g_Pt[4096 + k * 64 + n] = 2.f * a2 - (n == k ? 1.f : 0.f);
        g_Pt[2 * 4096 + k * 64 + n] = a3;
    }
    __syncthreads();
    for (int i = tid; i < 4096; i += 256) {
        int n = i >> 6, k = i & 63;
        float a4 = 0.f;
        for (int j = 0; j < 64; j++) a4 += s1[n * 64 + j] * g_Pt[2 * 4096 + k * 64 + j];
        g_Pt[3 * 4096 + k * 64 + n] = 2.f * a4 - s0[i];
    }
}

// ---------- weight repack ----------
__global__ void k_pack(const float* __restrict__ Wg0, const float* __restrict__ Wc0,
                       const float* __restrict__ Wg1, const float* __restrict__ Wc1) {
    const int WXsz = 5 * 64 * 192, WgHsz = 5 * 64 * 128, WcHsz = 5 * 64 * 64;
    const int PER_L = WXsz + WgHsz + WcHsz;
    for (int i = blockIdx.x * blockDim.x + threadIdx.x; i < 2 * PER_L; i += gridDim.x * blockDim.x) {
        int L = i / PER_L, r = i % PER_L;
        const float* Wg = L ? Wg1 : Wg0;
        const float* Wc = L ? Wc1 : Wc0;
        if (r < WXsz) {
            int m = r / (64 * 192), k = (r / 192) % 64, o = r % 192;
            g_WX[L][r] = (o < 128) ? Wg[(k * 5 + m) * 128 + o] : Wc[(k * 5 + m) * 64 + (o - 128)];
        } else if (r < WXsz + WgHsz) {
            int q = r - WXsz, m = q / (64 * 128), k = (q / 128) % 64, o = q % 128;
            g_WgH[L][q] = Wg[((64 + k) * 5 + m) * 128 + o];
        } else {
            int q = r - WXsz - WgHsz, m = q / 4096, k = (q / 64) % 64, o = q % 64;
            g_WcH[L][q] = Wc[((64 + k) * 5 + m) * 64 + o];
        }
    }
}

// ================= pre body (R12, proven bit-exact) =================
__device__ __forceinline__ void diffpre(const float* __restrict__ xN,
                                        const float* __restrict__ sP,
                                        float* __restrict__ xb,
                                        int pass, int grp, int n64) {
    int m = pass * 2 + (grp >> 2);
    int fg = grp & 3;
    const float* P = sP + m * 4096 + n64;
    const float* s = xN + fg * 16;
    ull d[8] = {0, 0, 0, 0, 0, 0, 0, 0};
#pragma unroll 2
    for (int k = 0; k < 64; k++) {
        float p = P[k * 64];
        ull p2 = pk2(p, p);
        const ulonglong2* hv = (const ulonglong2*)(s + k * 68);
        ulonglong2 a = hv[0], b = hv[1], c = hv[2], e = hv[3];
        ffma2(d[0], p2, a.x); ffma2(d[1], p2, a.y);
        ffma2(d[2], p2, b.x); ffma2(d[3], p2, b.y);
        ffma2(d[4], p2, c.x); ffma2(d[5], p2, c.y);
        ffma2(d[6], p2, e.x); ffma2(d[7], p2, e.y);
    }
    float* dst = xb + m * 4224 + fg * 16 * 66 + n64;
#pragma unroll
    for (int j = 0; j < 8; j++) {
        float x, y; upk2(d[j], x, y);
        dst[(2 * j) * 66] = x;
        dst[(2 * j + 1) * 66] = y;
    }
}

__device__ __forceinline__ void gemm_pre(const float* __restrict__ A,
                                         const float* __restrict__ B,
                                         ull* acc, int nl, int cg) {
#pragma unroll 2
    for (int k = 0; k < 64; k++) {
        float a0 = A[k * 66 + nl];
        float a1 = A[k * 66 + nl + 32];
        ull q0 = pk2(a0, a0), q1 = pk2(a1, a1);
        const ulonglong2* br = (const ulonglong2*)(B + k * 192 + cg * 12);
        ulonglong2 w0 = br[0], w1 = br[1], w2 = br[2];
        ffma2(acc[0], q0, w0.x); ffma2(acc[1], q0, w0.y);
        ffma2(acc[2], q0, w1.x); ffma2(acc[3], q0, w1.y);
        ffma2(acc[4], q0, w2.x); ffma2(acc[5], q0, w2.y);
        ffma2(acc[6], q1, w0.x); ffma2(acc[7], q1, w0.y);
        ffma2(acc[8], q1, w1.x); ffma2(acc[9], q1, w1.y);
        ffma2(acc[10], q1, w2.x); ffma2(acc[11], q1, w2.y);
    }
}

__device__ void pre_body(int layer, int t, int b, const float* __restrict__ xin,
                         const float* __restrict__ bg, const float* __restrict__ bc) {
    extern __shared__ float sm[];
    float* xT = sm;             // [64f][66]
    float* xN = sm + 4224;      // [64n][68]
    float* xb = sm + 8576;      // [4][64f][66]
    float* Bs = sm + 25472;     // [64][192]
    float* sP = sm + 37760;     // [4][64][64]
    const int tid = threadIdx.x;
    const int nl = tid & 31, cg = tid >> 5;
    const int n64 = tid & 63, grp = tid >> 6;

    const float* src = layer ? (g_Hseq + ((size_t)t * Bn + b) * 4096)
                             : (xin + ((size_t)b * Tn + t) * 4096);
    for (int i = tid; i < 1024; i += 512) {
        float4 v = __ldg((const float4*)src + i);
        int n = i >> 4, fo = (i & 15) << 2;
        *(float4*)&xN[n * 68 + fo] = v;
        xT[fo * 66 + n] = v.x; xT[(fo + 1) * 66 + n] = v.y;
        xT[(fo + 2) * 66 + n] = v.z; xT[(fo + 3) * 66 + n] = v.w;
    }
    for (int i = tid * 4; i < 16384; i += 2048)
        *(float4*)&sP[i] = *(const float4*)&g_Pt[i];
    const float4* W4 = (const float4*)g_WX[layer];
    float4 pf[6];
#pragma unroll
    for (int j = 0; j < 6; j++) pf[j] = W4[tid + j * 512];
    __syncthreads();

    ull acc[12] = {0, 0, 0, 0, 0, 0, 0, 0, 0, 0, 0, 0};
#pragma unroll
    for (int m = 0; m < 5; m++) {
#pragma unroll
        for (int j = 0; j < 6; j++) ((float4*)Bs)[tid + j * 512] = pf[j];
        if (m < 4) {
#pragma unroll
            for (int j = 0; j < 6; j++) pf[j] = W4[(m + 1) * 3072 + tid + j * 512];
        }
        if (m == 0) diffpre(xN, sP, xb, 0, grp, n64);
        if (m == 1) diffpre(xN, sP, xb, 1, grp, n64);
        __syncthreads();
        gemm_pre((m == 0) ? xT : (xb + (m - 1) * 4224), Bs, acc, nl, cg);
        __syncthreads();
    }

    size_t gb = ((size_t)t * Bn + b) * 64;
#pragma unroll
    for (int h = 0; h < 2; h++) {
        int n = nl + h * 32;
        float* Gp = g_Gx + (gb + n) * 128;
        float* Cp = g_Cx + (gb + n) * 64;
#pragma unroll
        for (int j = 0; j < 6; j++) {
            int o = cg * 12 + 2 * j;
            float lo, hi; upk2(acc[h * 6 + j], lo, hi);
            if (o < 128) {
                Gp[o] = lo + __ldg(bg + o);
                Gp[o + 1] = hi + __ldg(bg + o + 1);
            } else {
                Cp[o - 128] = lo + __ldg(bc + o - 128);
                Cp[o - 127] = hi + __ldg(bc + o - 127);
            }
        }
    }
}

// ================= recur (R12, proven bit-exact): staged weights, cluster DSMEM =================
__device__ __forceinline__ void diff1(const float* __restrict__ srcN,
                                      const float* __restrict__ sPh,
                                      float* __restrict__ xb,
                                      int w, int nl) {
    int m = w >> 2;
    int fg = w & 3;
    const float* P = sPh + m * 2048 + nl;
    const float* s = srcN + fg * 16;
    ull d[8] = {0, 0, 0, 0, 0, 0, 0, 0};
#pragma unroll 2
    for (int k = 0; k < 64; k++) {
        float p = P[k * 32];
        ull p2 = pk2(p, p);
        const ulonglong2* hv = (const ulonglong2*)(s + k * 68);
        ulonglong2 a = hv[0], b = hv[1], c = hv[2], e = hv[3];
        ffma2(d[0], p2, a.x); ffma2(d[1], p2, a.y);
        ffma2(d[2], p2, b.x); ffma2(d[3], p2, b.y);
        ffma2(d[4], p2, c.x); ffma2(d[5], p2, c.y);
        ffma2(d[6], p2, e.x); ffma2(d[7], p2, e.y);
    }
    float* dst = xb + m * 2176 + fg * 16 * 34 + nl;
#pragma unroll
    for (int j = 0; j < 8; j++) {
        float x, y; upk2(d[j], x, y);
        dst[(2 * j) * 34] = x;
        dst[(2 * j + 1) * 34] = y;
    }
}

__device__ __forceinline__ void gemm_gate(const float* __restrict__ A,
                                          const float* __restrict__ B,
                                          ull* acc, int nl, int cg) {
#pragma unroll 4
    for (int k = 0; k < 64; k++) {
        float a = A[k * 34 + nl];
        ull a2 = pk2(a, a);
        const ulonglong2* br = (const ulonglong2*)(B + k * 128 + cg * 8);
        ulonglong2 w0 = br[0], w1 = br[1];
        ffma2(acc[0], a2, w0.x); ffma2(acc[1], a2, w0.y);
        ffma2(acc[2], a2, w1.x); ffma2(acc[3], a2, w1.y);
    }
}
__device__ __forceinline__ void gemm_cand(const float* __restrict__ A,
                                          const float* __restrict__ B,
                                          ull* acc, int nl, int cg) {
#pragma unroll 4
    for (int k = 0; k < 64; k++) {
        float a = A[k * 34 + nl];
        ull a2 = pk2(a, a);
        ulonglong2 w = *(const ulonglong2*)(B + k * 64 + cg * 4);
        ffma2(acc[0], a2, w.x); ffma2(acc[1], a2, w.y);
    }
}

template <int LAYER, bool PUBLISH, bool WAITPRE>
__device__ void recur_body(int b, const int* __restrict__ seql) {
    extern __shared__ float sm[];
    float* Bs  = sm;                  // [2][8192]
    float* hN  = sm + 16384;          // [64][68]
    float* rhN = hN + 4352;           // [64][68]
    float* sPh = rhN + 4352;          // [4][64k][32n]
    float* hT  = sPh + 8192;          // [64f][34]
    float* rhT = hT + 2176;           // [64f][34]
    float* uT  = rhT + 2176;          // [64o][34]
    float* xb  = uT + 2176;           // [4][64f][34]

    const int tid = threadIdx.x;
    const int hf = blockIdx.x & 1;    // cluster rank
    const int nl = tid & 31;
    const int cg = tid >> 5;          // warp id 0..15
    const int ng = hf * 32 + nl;
    const unsigned peer_rank = hf ^ 1;

    for (int i = tid; i < 8192; i += 512) {
        int m = i >> 11, r = i & 2047, k = r >> 5, nn = r & 31;
        sPh[i] = g_Pt[m * 4096 + k * 64 + hf * 32 + nn];
    }
    for (int i = tid; i < 64 * 68; i += 512) hN[i] = 0.f;
    for (int i = tid; i < 64 * 34; i += 512) hT[i] = 0.f;
    const unsigned rhN_rem = mapa_rank(s2u(&rhN[ng * 68]), peer_rank);
    const unsigned hN_rem  = mapa_rank(s2u(&hN[ng * 68]),  peer_rank);
    CLUSTER_SYNC();

    const float4* Wg4 = (const float4*)g_WgH[LAYER];
    const float4* Wc4 = (const float4*)g_WcH[LAYER];
    const int last_t = seql[b] - 1;

    for (int t = 0; t <= last_t; t++) {
        if (WAITPRE) {
            if (tid == 0) {
                const int* f = &g_prog1[t * Bn + b];
                while (flag_acq(f) < 1) __nanosleep(128);
            }
            __syncthreads();
        }
        // ================= GATE =================
        {
            const float* GxP = g_Gx + (((size_t)t * Bn + b) * 64 + ng) * 128 + cg * 8;
            float4 gx0 = __ldg((const float4*)GxP);
            float4 gx1 = __ldg((const float4*)GxP + 1);
            ull acc[4] = {0, 0, 0, 0};
            float4 pf0 = Wg4[tid], pf1 = Wg4[tid + 512], pf2 = Wg4[tid + 1024], pf3 = Wg4[tid + 1536];
            ((float4*)Bs)[tid] = pf0; ((float4*)Bs)[tid + 512] = pf1;
            ((float4*)Bs)[tid + 1024] = pf2; ((float4*)Bs)[tid + 1536] = pf3;
            pf0 = Wg4[2048 + tid]; pf1 = Wg4[2048 + tid + 512];
            pf2 = Wg4[2048 + tid + 1024]; pf3 = Wg4[2048 + tid + 1536];
            diff1(hN, sPh, xb, cg, nl);
            __syncthreads();
#pragma unroll
            for (int m = 0; m < 5; m++) {
                gemm_gate((m == 0) ? hT : (xb + (m - 1) * 2176), Bs + (m & 1) * 8192, acc, nl, cg);
                if (m < 4) {
                    float4* d = (float4*)(Bs + ((m + 1) & 1) * 8192);
                    d[tid] = pf0; d[tid + 512] = pf1; d[tid + 1024] = pf2; d[tid + 1536] = pf3;
                    if (m < 3) {
                        pf0 = Wg4[(m + 2) * 2048 + tid];        pf1 = Wg4[(m + 2) * 2048 + tid + 512];
                        pf2 = Wg4[(m + 2) * 2048 + tid + 1024]; pf3 = Wg4[(m + 2) * 2048 + tid + 1536];
                    }
                    __syncthreads();
                }
            }
            float gx[8] = {gx0.x, gx0.y, gx0.z, gx0.w, gx1.x, gx1.y, gx1.z, gx1.w};
            if (cg < 8) {
                float rv[8];
#pragma unroll
                for (int j = 0; j < 4; j++) {
                    int o = cg * 8 + 2 * j;
                    float lo, hi; upk2(acc[j], lo, hi);
                    float h0 = hT[o * 34 + nl], h1 = hT[(o + 1) * 34 + nl];
                    float r0 = sigm(lo + gx[2 * j]) * h0;
                    float r1 = sigm(hi + gx[2 * j + 1]) * h1;
                    rhN[ng * 68 + o] = r0; rhN[ng * 68 + o + 1] = r1;
                    rhT[o * 34 + nl] = r0; rhT[(o + 1) * 34 + nl] = r1;
                    rv[2 * j] = r0; rv[2 * j + 1] = r1;
                }
                st_rem_v4(rhN_rem + cg * 32, make_float4(rv[0], rv[1], rv[2], rv[3]));
                st_rem_v4(rhN_rem + cg * 32 + 16, make_float4(rv[4], rv[5], rv[6], rv[7]));
            } else {
#pragma unroll
                for (int j = 0; j < 4; j++) {
                    int o = cg * 8 + 2 * j;
                    float lo, hi; upk2(acc[j], lo, hi);
                    uT[(o - 64) * 34 + nl] = sigm(lo + gx[2 * j]);
                    uT[(o - 63) * 34 + nl] = sigm(hi + gx[2 * j + 1]);
                }
            }
        }
        CLUSTER_SYNC();

        // ================= CAND =================
        {
            const float* CxP = g_Cx + (((size_t)t * Bn + b) * 64 + ng) * 64 + cg * 4;
            float4 cx = __ldg((const float4*)CxP);
            ull acc[2] = {0, 0};
            float4 pc0 = Wc4[tid], pc1 = Wc4[tid + 512];
            ((float4*)Bs)[tid] = pc0; ((float4*)Bs)[tid + 512] = pc1;
            pc0 = Wc4[1024 + tid]; pc1 = Wc4[1024 + tid + 512];
            diff1(rhN, sPh, xb, cg, nl);
            __syncthreads();
#pragma unroll
            for (int m = 0; m < 5; m++) {
                gemm_cand((m == 0) ? rhT : (xb + (m - 1) * 2176), Bs + (m & 1) * 8192, acc, nl, cg);
                if (m < 4) {
                    float4* d = (float4*)(Bs + ((m + 1) & 1) * 8192);
                    d[tid] = pc0; d[tid + 512] = pc1;
                    if (m < 3) {
                        pc0 = Wc4[(m + 2) * 1024 + tid];
                        pc1 = Wc4[(m + 2) * 1024 + tid + 512];
                    }
                    __syncthreads();
                }
            }
            float cxv[4] = {cx.x, cx.y, cx.z, cx.w};
            float hv[4];
            bool isLast = (LAYER == 1) && (t == last_t);
#pragma unroll
            for (int j = 0; j < 2; j++) {
                int o = cg * 4 + 2 * j;
                float lo, hi; upk2(acc[j], lo, hi);
                float c0 = tanhfast(lo + cxv[2 * j]);
                float c1 = tanhfast(hi + cxv[2 * j + 1]);
                float u0 = uT[o * 34 + nl], u1 = uT[(o + 1) * 34 + nl];
                float h0 = hT[o * 34 + nl], h1 = hT[(o + 1) * 34 + nl];
                hv[2 * j] = u0 * h0 + (1.f - u0) * c0;
                hv[2 * j + 1] = u1 * h1 + (1.f - u1) * c1;
            }
#pragma unroll
            for (int j = 0; j < 2; j++) {
                int o = cg * 4 + 2 * j;
                hN[ng * 68 + o] = hv[2 * j]; hN[ng * 68 + o + 1] = hv[2 * j + 1];
                hT[o * 34 + nl] = hv[2 * j]; hT[(o + 1) * 34 + nl] = hv[2 * j + 1];
            }
            float4 hq = make_float4(hv[0], hv[1], hv[2], hv[3]);
            st_rem_v4(hN_rem + cg * 16, hq);
            if (LAYER == 0)
                *(float4*)(g_Hseq + ((size_t)t * Bn + b) * 4096 + ng * 64 + cg * 4) = hq;
            if (isLast)
                *(float4*)(g_Last + (size_t)(b * 64 + ng) * 64 + cg * 4) = hq;
        }
        CLUSTER_SYNC();
        if (PUBLISH && tid == 0) flag_release(&g_prog[b * 2 + hf]);
    }
}

// ---------- standalone layer-0 pre ----------
__global__ void __launch_bounds__(512, 1) k_pre0(const float* __restrict__ xin,
                                                 const float* __restrict__ bg,
                                                 const float* __restrict__ bc,
                                                 const int* __restrict__ seql) {
    int t = blockIdx.x, b = blockIdx.y;
    if (t >= seql[b]) return;
    pre_body(0, t, b, xin, bg, bc);
}

// ---------- fused: recur0 + pre1 + recur1, all overlapped via flags ----------
// y in [0,Bn): recur0 for batch y (publishes g_prog)
// y in [Bn, Bn+3072): pre1, gated on g_prog (publishes g_prog1)
// y in [Bn+3072, Bn+3072+Bn): recur1 for batch y-Bn-3072, gated on g_prog1
__global__ void __launch_bounds__(512, 1) __cluster_dims__(2, 1, 1)
k_fused(const float* __restrict__ bg1, const float* __restrict__ bc1,
        const int* __restrict__ seql) {
    const int PRE_Y = Bn + (Tn * Bn) / 2;
    if (blockIdx.y < Bn) {
        recur_body<0, true, false>(blockIdx.y, seql);
    } else if (blockIdx.y < PRE_Y) {
        int p = (blockIdx.y - Bn) * 2 + blockIdx.x;   // 0..6143, t slow-varying
        int t = p / Bn, b = p % Bn;
        if (t >= seql[b]) return;
        if (threadIdx.x == 0) {
            const int* p0 = &g_prog[b * 2];
            const int* p1 = &g_prog[b * 2 + 1];
            while (flag_acq(p0) <= t) __nanosleep(256);
            while (flag_acq(p1) <= t) __nanosleep(256);
        }
        __syncthreads();
        pre_body(1, t, b, nullptr, bg1, bc1);
        __syncthreads();
        if (threadIdx.x == 0) flag_release(&g_prog1[t * Bn + b]);
    } else {
        recur_body<1, false, true>(blockIdx.y - PRE_Y, seql);
    }
}

// ---------- output head ----------
__global__ void k_head(const float* __restrict__ fcw, const float* __restrict__ fcb,
                       const float* __restrict__ idw, const float* __restrict__ idb,
                       float* __restrict__ out) {
    __shared__ float hb[4096];
    __shared__ float w[64 * 54];
    __shared__ float bias[54];
    int b = blockIdx.x, tid = threadIdx.x;
    for (int i = tid; i < 4096; i += 256) hb[i] = fmaxf(g_Last[b * 4096 + i], 0.f);
    for (int i = tid; i < 64 * 54; i += 256) {
        int k = i / 54, c = i % 54;
        w[i] = (c < 4) ? fcw[k * 4 + c] : idw[k * 50 + c - 4];
    }
    if (tid < 54) bias[tid] = (tid < 4) ? fcb[tid] : idb[tid - 4];
    __syncthreads();
    if (tid < 54) {
        float best = -INFINITY;
        for (int nn = 0; nn < 64; nn++) {
            float s = bias[tid];
            for (int k = 0; k < 64; k++) s += hb[nn * 64 + k] * w[k * 54 + tid];
            best = fmaxf(best, s);
        }
        if (tid < 4) out[b * 4 + tid] = best;
        else out[256 + b * 50 + tid - 4] = best;
    }
}

extern "C" void kernel_launch(void* const* d_in, const int* in_sizes, int n_in,
                              void* d_out, int out_size) {
    const float* xseq = (const float*)d_in[0];
    const int* seql = (const int*)d_in[1];
    const float* S0 = (const float*)d_in[2];
    const float* S1 = (const float*)d_in[3];
    const float* Wg0 = (const float*)d_in[4]; const float* bg0 = (const float*)d_in[5];
    const float* Wc0 = (const float*)d_in[6]; const float* bc0 = (const float*)d_in[7];
    const float* Wg1 = (const float*)d_in[8]; const float* bg1 = (const float*)d_in[9];
    const float* Wc1 = (const float*)d_in[10]; const float* bc1 = (const float*)d_in[11];
    const float* fcw = (const float*)d_in[12]; const float* fcb = (const float*)d_in[13];
    const float* idw = (const float*)d_in[14]; const float* idb = (const float*)d_in[15];
    float* out = (float*)d_out;

    const int SM_PRE = (4224 + 4352 + 16896 + 12288 + 16384) * 4;   // 216576
    cudaFuncSetAttribute(k_pre0, cudaFuncAttributeMaxDynamicSharedMemorySize, SM_PRE);
    cudaFuncSetAttribute(k_fused, cudaFuncAttributeMaxDynamicSharedMemorySize, SM_PRE);

    k_prep<<<1, 256>>>(S0, S1);
    k_pack<<<240, 256>>>(Wg0, Wc0, Wg1, Wc1);

    k_pre0<<<dim3(Tn, Bn), 512, SM_PRE>>>(xseq, bg0, bc0, seql);
    k_fused<<<dim3(2, Bn + (Tn * Bn) / 2 + Bn), 512, SM_PRE>>>(bg1, bc1, seql);

    k_head<<<Bn, 256>>>(fcw, fcb, idw, idb, out);
}

// round 17
// speedup vs baseline: 1.0051x; 1.0051x over previous
#include <cuda_runtime.h>
#include <math.h>

typedef unsigned long long ull;
#define Tn 96
#define Bn 64

__device__ __forceinline__ ull pk2(float lo, float hi) {
    ull r; asm("mov.b64 %0,{%1,%2};" : "=l"(r) : "f"(lo), "f"(hi)); return r;
}
__device__ __forceinline__ void upk2(ull v, float &a, float &b) {
    asm("mov.b64 {%0,%1},%2;" : "=f"(a), "=f"(b) : "l"(v));
}
__device__ __forceinline__ void ffma2(ull &d, ull a, ull b) {
    asm("fma.rn.f32x2 %0,%1,%2,%0;" : "+l"(d) : "l"(a), "l"(b));
}
__device__ __forceinline__ float sigm(float x) { return 1.f / (1.f + __expf(-x)); }
__device__ __forceinline__ float tanhfast(float x) {
    float t = __expf(-2.f * fabsf(x));
    return copysignf((1.f - t) / (1.f + t), x);
}
__device__ __forceinline__ unsigned s2u(const void* p) {
    unsigned a;
    asm("{ .reg .u64 t; cvta.to.shared.u64 t, %1; cvt.u32.u64 %0, t; }" : "=r"(a) : "l"(p));
    return a;
}
__device__ __forceinline__ unsigned mapa_rank(unsigned a, unsigned rank) {
    unsigned r; asm("mapa.shared::cluster.u32 %0, %1, %2;" : "=r"(r) : "r"(a), "r"(rank));
    return r;
}
__device__ __forceinline__ void st_rem_v4(unsigned a, float4 v) {
    asm volatile("st.shared::cluster.v4.f32 [%0], {%1,%2,%3,%4};"
                 :: "r"(a), "f"(v.x), "f"(v.y), "f"(v.z), "f"(v.w) : "memory");
}
__device__ __forceinline__ void flag_release(int* p) {
    asm volatile("red.release.gpu.global.add.s32 [%0], 1;" :: "l"(p) : "memory");
}
__device__ __forceinline__ int flag_acq(const int* p) {
    int v; asm volatile("ld.acquire.gpu.global.s32 %0, [%1];" : "=r"(v) : "l"(p) : "memory");
    return v;
}
#define CLUSTER_SYNC() do { \
    asm volatile("barrier.cluster.arrive.aligned;" ::: "memory"); \
    asm volatile("barrier.cluster.wait.aligned;" ::: "memory"); \
} while (0)

// ---------- device-global scratch ----------
__device__ __align__(256) float g_Pt[4 * 4096];
__device__ __align__(256) float g_WX[2][5 * 64 * 192];
__device__ __align__(256) float g_WgH[2][5 * 64 * 128];
__device__ __align__(256) float g_WcH[2][5 * 64 * 64];
__device__ __align__(256) float g_Gx[(size_t)Tn * Bn * 64 * 128];
__device__ __align__(256) float g_Cx[(size_t)Tn * Bn * 64 * 64];
__device__ __align__(256) float g_Hseq[(size_t)Tn * Bn * 4096];
__device__ __align__(256) float g_Last[Bn * 4096];
__device__ __align__(256) int   g_prog[128];
__device__ __align__(256) int   g_prog1[Tn * Bn];

// ---------- P matrices ----------
__global__ void k_prep(const float* __restrict__ S0, const float* __restrict__ S1) {
    __shared__ float s0[4096], s1[4096];
    int tid = threadIdx.x;
    if (tid < 128) g_prog[tid] = 0;
    for (int i = tid; i < Tn * Bn; i += 256) g_prog1[i] = 0;
    for (int i = tid; i < 4096; i += 256) { s0[i] = S0[i]; s1[i] = S1[i]; }
    __syncthreads();
    for (int i = tid; i < 4096; i += 256) {
        int n = i >> 6, k = i & 63;
        float a2 = 0.f, a3 = 0.f;
        for (int j = 0; j < 64; j++) {
            a2 += s0[n * 64 + j] * s0[j * 64 + k];
            a3 += s1[n * 64 + j] * s0[j * 64 + k];
        }
        g_Pt[k * 64 + n] = s0[i];
        g_Pt[4096 + k * 64 + n] = 2.f * a2 - (n == k ? 1.f : 0.f);
        g_Pt[2 * 4096 + k * 64 + n] = a3;
    }
    __syncthreads();
    for (int i = tid; i < 4096; i += 256) {
        int n = i >> 6, k = i & 63;
        float a4 = 0.f;
        for (int j = 0; j < 64; j++) a4 += s1[n * 64 + j] * g_Pt[2 * 4096 + k * 64 + j];
        g_Pt[3 * 4096 + k * 64 + n] = 2.f * a4 - s0[i];
    }
}

// ---------- weight repack ----------
__global__ void k_pack(const float* __restrict__ Wg0, const float* __restrict__ Wc0,
                       const float* __restrict__ Wg1, const float* __restrict__ Wc1) {
    const int WXsz = 5 * 64 * 192, WgHsz = 5 * 64 * 128, WcHsz = 5 * 64 * 64;
    const int PER_L = WXsz + WgHsz + WcHsz;
    for (int i = blockIdx.x * blockDim.x + threadIdx.x; i < 2 * PER_L; i += gridDim.x * blockDim.x) {
        int L = i / PER_L, r = i % PER_L;
        const float* Wg = L ? Wg1 : Wg0;
        const float* Wc = L ? Wc1 : Wc0;
        if (r < WXsz) {
            int m = r / (64 * 192), k = (r / 192) % 64, o = r % 192;
            g_WX[L][r] = (o < 128) ? Wg[(k * 5 + m) * 128 + o] : Wc[(k * 5 + m) * 64 + (o - 128)];
        } else if (r < WXsz + WgHsz) {
            int q = r - WXsz, m = q / (64 * 128), k = (q / 128) % 64, o = q % 128;
            g_WgH[L][q] = Wg[((64 + k) * 5 + m) * 128 + o];
        } else {
            int q = r - WXsz - WgHsz, m = q / 4096, k = (q / 64) % 64, o = q % 64;
            g_WcH[L][q] = Wc[((64 + k) * 5 + m) * 64 + o];
        }
    }
}

// ================= pre body FULL (R12 proven; used inside k_fused for pre1) =================
__device__ __forceinline__ void diffpre(const float* __restrict__ xN,
                                        const float* __restrict__ sP,
                                        float* __restrict__ xb,
                                        int pass, int grp, int n64) {
    int m = pass * 2 + (grp >> 2);
    int fg = grp & 3;
    const float* P = sP + m * 4096 + n64;
    const float* s = xN + fg * 16;
    ull d[8] = {0, 0, 0, 0, 0, 0, 0, 0};
#pragma unroll 2
    for (int k = 0; k < 64; k++) {
        float p = P[k * 64];
        ull p2 = pk2(p, p);
        const ulonglong2* hv = (const ulonglong2*)(s + k * 68);
        ulonglong2 a = hv[0], b = hv[1], c = hv[2], e = hv[3];
        ffma2(d[0], p2, a.x); ffma2(d[1], p2, a.y);
        ffma2(d[2], p2, b.x); ffma2(d[3], p2, b.y);
        ffma2(d[4], p2, c.x); ffma2(d[5], p2, c.y);
        ffma2(d[6], p2, e.x); ffma2(d[7], p2, e.y);
    }
    float* dst = xb + m * 4224 + fg * 16 * 66 + n64;
#pragma unroll
    for (int j = 0; j < 8; j++) {
        float x, y; upk2(d[j], x, y);
        dst[(2 * j) * 66] = x;
        dst[(2 * j + 1) * 66] = y;
    }
}

__device__ __forceinline__ void gemm_pre(const float* __restrict__ A, int lda,
                                         const float* __restrict__ B,
                                         ull* acc, int nl, int cg) {
#pragma unroll 2
    for (int k = 0; k < 64; k++) {
        float a0 = A[k * lda + nl];
        float a1 = A[k * lda + nl + 32];
        ull q0 = pk2(a0, a0), q1 = pk2(a1, a1);
        const ulonglong2* br = (const ulonglong2*)(B + k * 192 + cg * 12);
        ulonglong2 w0 = br[0], w1 = br[1], w2 = br[2];
        ffma2(acc[0], q0, w0.x); ffma2(acc[1], q0, w0.y);
        ffma2(acc[2], q0, w1.x); ffma2(acc[3], q0, w1.y);
        ffma2(acc[4], q0, w2.x); ffma2(acc[5], q0, w2.y);
        ffma2(acc[6], q1, w0.x); ffma2(acc[7], q1, w0.y);
        ffma2(acc[8], q1, w1.x); ffma2(acc[9], q1, w1.y);
        ffma2(acc[10], q1, w2.x); ffma2(acc[11], q1, w2.y);
    }
}

__device__ __forceinline__ void pre_store(ull* acc, int t, int b, int nl, int cg,
                                          const float* __restrict__ bg,
                                          const float* __restrict__ bc) {
    size_t gb = ((size_t)t * Bn + b) * 64;
#pragma unroll
    for (int h = 0; h < 2; h++) {
        int n = nl + h * 32;
        float* Gp = g_Gx + (gb + n) * 128;
        float* Cp = g_Cx + (gb + n) * 64;
#pragma unroll
        for (int j = 0; j < 6; j++) {
            int o = cg * 12 + 2 * j;
            float lo, hi; upk2(acc[h * 6 + j], lo, hi);
            if (o < 128) {
                Gp[o] = lo + __ldg(bg + o);
                Gp[o + 1] = hi + __ldg(bg + o + 1);
            } else {
                Cp[o - 128] = lo + __ldg(bc + o - 128);
                Cp[o - 127] = hi + __ldg(bc + o - 127);
            }
        }
    }
}

__device__ void pre_body(int layer, int t, int b, const float* __restrict__ xin,
                         const float* __restrict__ bg, const float* __restrict__ bc) {
    extern __shared__ float sm[];
    float* xT = sm;             // [64f][66]
    float* xN = sm + 4224;      // [64n][68]
    float* xb = sm + 8576;      // [4][64f][66]
    float* Bs = sm + 25472;     // [64][192]
    float* sP = sm + 37760;     // [4][64][64]
    const int tid = threadIdx.x;
    const int nl = tid & 31, cg = tid >> 5;
    const int n64 = tid & 63, grp = tid >> 6;

    const float* src = layer ? (g_Hseq + ((size_t)t * Bn + b) * 4096)
                             : (xin + ((size_t)b * Tn + t) * 4096);
    for (int i = tid; i < 1024; i += 512) {
        float4 v = __ldg((const float4*)src + i);
        int n = i >> 4, fo = (i & 15) << 2;
        *(float4*)&xN[n * 68 + fo] = v;
        xT[fo * 66 + n] = v.x; xT[(fo + 1) * 66 + n] = v.y;
        xT[(fo + 2) * 66 + n] = v.z; xT[(fo + 3) * 66 + n] = v.w;
    }
    for (int i = tid * 4; i < 16384; i += 2048)
        *(float4*)&sP[i] = *(const float4*)&g_Pt[i];
    const float4* W4 = (const float4*)g_WX[layer];
    float4 pf[6];
#pragma unroll
    for (int j = 0; j < 6; j++) pf[j] = W4[tid + j * 512];
    __syncthreads();

    ull acc[12] = {0, 0, 0, 0, 0, 0, 0, 0, 0, 0, 0, 0};
#pragma unroll
    for (int m = 0; m < 5; m++) {
#pragma unroll
        for (int j = 0; j < 6; j++) ((float4*)Bs)[tid + j * 512] = pf[j];
        if (m < 4) {
#pragma unroll
            for (int j = 0; j < 6; j++) pf[j] = W4[(m + 1) * 3072 + tid + j * 512];
        }
        if (m == 0) diffpre(xN, sP, xb, 0, grp, n64);
        if (m == 1) diffpre(xN, sP, xb, 1, grp, n64);
        __syncthreads();
        gemm_pre((m == 0) ? xT : (xb + (m - 1) * 4224), 66, Bs, acc, nl, cg);
        __syncthreads();
    }
    pre_store(acc, t, b, nl, cg, bg, bc);
}

// ================= pre body DIET (99,328 B smem; bit-exact; 2 CTAs/SM) =================
// smem floats: buf [8192] @0 (xT = buf[0..4096) until m=0 done; then xb 2 slots of 4096)
//              xN [64][68] @8192 | Bs [64][192] @12544 .. 24832
__device__ __forceinline__ void diffpre0(const float* __restrict__ xN,
                                         float* __restrict__ buf,
                                         int pass, int grp, int n64) {
    int m = pass * 2 + (grp >> 2);
    int slot = grp >> 2;
    int fg = grp & 3;
    const float* P = g_Pt + m * 4096 + n64;
    const float* s = xN + fg * 16;
    ull d[8] = {0, 0, 0, 0, 0, 0, 0, 0};
#pragma unroll 2
    for (int k = 0; k < 64; k++) {
        float p = __ldg(P + k * 64);
        ull p2 = pk2(p, p);
        const ulonglong2* hv = (const ulonglong2*)(s + k * 68);
        ulonglong2 a = hv[0], b = hv[1], c = hv[2], e = hv[3];
        ffma2(d[0], p2, a.x); ffma2(d[1], p2, a.y);
        ffma2(d[2], p2, b.x); ffma2(d[3], p2, b.y);
        ffma2(d[4], p2, c.x); ffma2(d[5], p2, c.y);
        ffma2(d[6], p2, e.x); ffma2(d[7], p2, e.y);
    }
    float* dst = buf + slot * 4096 + fg * 16 * 64 + n64;
#pragma unroll
    for (int j = 0; j < 8; j++) {
        float x, y; upk2(d[j], x, y);
        dst[(2 * j) * 64] = x;
        dst[(2 * j + 1) * 64] = y;
    }
}

__device__ __forceinline__ void stageW0(float* __restrict__ Bs, int m, int tid) {
    const float4* W4 = (const float4*)(g_WX[0] + m * 12288);
    float4* d4 = (float4*)Bs;
#pragma unroll
    for (int j = 0; j < 6; j++) d4[tid + j * 512] = __ldg(W4 + tid + j * 512);
}

__global__ void __launch_bounds__(512, 2) k_pre0(const float* __restrict__ xin,
                                                 const float* __restrict__ bg,
                                                 const float* __restrict__ bc,
                                                 const int* __restrict__ seql) {
    const int t = blockIdx.x, b = blockIdx.y;
    if (t >= seql[b]) return;
    extern __shared__ float sm[];
    float* buf = sm;            // xT then xb[2][64][64]
    float* xN  = sm + 8192;     // [64][68]
    float* Bs  = sm + 12544;    // [64][192]
    const int tid = threadIdx.x;
    const int nl = tid & 31, cg = tid >> 5;
    const int n64 = tid & 63, grp = tid >> 6;

    const float* src = xin + ((size_t)b * Tn + t) * 4096;
    for (int i = tid; i < 1024; i += 512) {
        float4 v = __ldg((const float4*)src + i);
        int n = i >> 4, fo = (i & 15) << 2;
        *(float4*)&xN[n * 68 + fo] = v;
        buf[fo * 64 + n] = v.x; buf[(fo + 1) * 64 + n] = v.y;
        buf[(fo + 2) * 64 + n] = v.z; buf[(fo + 3) * 64 + n] = v.w;
    }
    stageW0(Bs, 0, tid);
    __syncthreads();

    ull acc[12] = {0, 0, 0, 0, 0, 0, 0, 0, 0, 0, 0, 0};
    gemm_pre(buf, 64, Bs, acc, nl, cg);        // m=0 reads xT (buf)
    __syncthreads();                           // xT dead; buf reusable
    diffpre0(xN, buf, 0, grp, n64);            // P1,P2 -> slots 0,1
    stageW0(Bs, 1, tid);
    __syncthreads();
    gemm_pre(buf, 64, Bs, acc, nl, cg);        // m=1 (slot 0)
    __syncthreads();
    stageW0(Bs, 2, tid);
    __syncthreads();
    gemm_pre(buf + 4096, 64, Bs, acc, nl, cg); // m=2 (slot 1)
    __syncthreads();                           // xb consumed
    diffpre0(xN, buf, 1, grp, n64);            // P3,P4 -> slots 0,1
    stageW0(Bs, 3, tid);
    __syncthreads();
    gemm_pre(buf, 64, Bs, acc, nl, cg);        // m=3 (slot 0)
    __syncthreads();
    stageW0(Bs, 4, tid);
    __syncthreads();
    gemm_pre(buf + 4096, 64, Bs, acc, nl, cg); // m=4 (slot 1)

    pre_store(acc, t, b, nl, cg, bg, bc);
}

// ================= recur (proven bit-exact) =================
__device__ __forceinline__ void diff1(const float* __restrict__ srcN,
                                      const float* __restrict__ sPh,
                                      float* __restrict__ xb,
                                      int w, int nl) {
    int m = w >> 2;
    int fg = w & 3;
    const float* P = sPh + m * 2048 + nl;
    const float* s = srcN + fg * 16;
    ull d[8] = {0, 0, 0, 0, 0, 0, 0, 0};
#pragma unroll 2
    for (int k = 0; k < 64; k++) {
        float p = P[k * 32];
        ull p2 = pk2(p, p);
        const ulonglong2* hv = (const ulonglong2*)(s + k * 68);
        ulonglong2 a = hv[0], b = hv[1], c = hv[2], e = hv[3];
        ffma2(d[0], p2, a.x); ffma2(d[1], p2, a.y);
        ffma2(d[2], p2, b.x); ffma2(d[3], p2, b.y);
        ffma2(d[4], p2, c.x); ffma2(d[5], p2, c.y);
        ffma2(d[6], p2, e.x); ffma2(d[7], p2, e.y);
    }
    float* dst = xb + m * 2176 + fg * 16 * 34 + nl;
#pragma unroll
    for (int j = 0; j < 8; j++) {
        float x, y; upk2(d[j], x, y);
        dst[(2 * j) * 34] = x;
        dst[(2 * j + 1) * 34] = y;
    }
}

__device__ __forceinline__ void gemm_gate(const float* __restrict__ A,
                                          const float* __restrict__ B,
                                          ull* acc, int nl, int cg) {
#pragma unroll 4
    for (int k = 0; k < 64; k++) {
        float a = A[k * 34 + nl];
        ull a2 = pk2(a, a);
        const ulonglong2* br = (const ulonglong2*)(B + k * 128 + cg * 8);
        ulonglong2 w0 = br[0], w1 = br[1];
        ffma2(acc[0], a2, w0.x); ffma2(acc[1], a2, w0.y);
        ffma2(acc[2], a2, w1.x); ffma2(acc[3], a2, w1.y);
    }
}
__device__ __forceinline__ void gemm_cand(const float* __restrict__ A,
                                          const float* __restrict__ B,
                                          ull* acc, int nl, int cg) {
#pragma unroll 4
    for (int k = 0; k < 64; k++) {
        float a = A[k * 34 + nl];
        ull a2 = pk2(a, a);
        ulonglong2 w = *(const ulonglong2*)(B + k * 64 + cg * 4);
        ffma2(acc[0], a2, w.x); ffma2(acc[1], a2, w.y);
    }
}

template <int LAYER, bool PUBLISH, bool WAITPRE>
__device__ void recur_body(int b, const int* __restrict__ seql) {
    extern __shared__ float sm[];
    float* Bs  = sm;                  // [2][8192]
    float* hN  = sm + 16384;          // [64][68]
    float* rhN = hN + 4352;           // [64][68]
    float* sPh = rhN + 4352;          // [4][64k][32n]
    float* hT  = sPh + 8192;          // [64f][34]
    float* rhT = hT + 2176;           // [64f][34]
    float* uT  = rhT + 2176;          // [64o][34]
    float* xb  = uT + 2176;           // [4][64f][34]

    const int tid = threadIdx.x;
    const int hf = blockIdx.x & 1;
    const int nl = tid & 31;
    const int cg = tid >> 5;
    const int ng = hf * 32 + nl;
    const unsigned peer_rank = hf ^ 1;

    for (int i = tid; i < 8192; i += 512) {
        int m = i >> 11, r = i & 2047, k = r >> 5, nn = r & 31;
        sPh[i] = g_Pt[m * 4096 + k * 64 + hf * 32 + nn];
    }
    for (int i = tid; i < 64 * 68; i += 512) hN[i] = 0.f;
    for (int i = tid; i < 64 * 34; i += 512) hT[i] = 0.f;
    const unsigned rhN_rem = mapa_rank(s2u(&rhN[ng * 68]), peer_rank);
    const unsigned hN_rem  = mapa_rank(s2u(&hN[ng * 68]),  peer_rank);
    CLUSTER_SYNC();

    const float4* Wg4 = (const float4*)g_WgH[LAYER];
    const float4* Wc4 = (const float4*)g_WcH[LAYER];
    const int last_t = seql[b] - 1;

    for (int t = 0; t <= last_t; t++) {
        if (WAITPRE) {
            if (tid == 0) {
                const int* f = &g_prog1[t * Bn + b];
                while (flag_acq(f) < 1) __nanosleep(128);
            }
            __syncthreads();
        }
        // ===== GATE =====
        {
            const float* GxP = g_Gx + (((size_t)t * Bn + b) * 64 + ng) * 128 + cg * 8;
            float4 gx0 = __ldg((const float4*)GxP);
            float4 gx1 = __ldg((const float4*)GxP + 1);
            ull acc[4] = {0, 0, 0, 0};
            float4 pf0 = Wg4[tid], pf1 = Wg4[tid + 512], pf2 = Wg4[tid + 1024], pf3 = Wg4[tid + 1536];
            ((float4*)Bs)[tid] = pf0; ((float4*)Bs)[tid + 512] = pf1;
            ((float4*)Bs)[tid + 1024] = pf2; ((float4*)Bs)[tid + 1536] = pf3;
            pf0 = Wg4[2048 + tid]; pf1 = Wg4[2048 + tid + 512];
            pf2 = Wg4[2048 + tid + 1024]; pf3 = Wg4[2048 + tid + 1536];
            diff1(hN, sPh, xb, cg, nl);
            __syncthreads();
#pragma unroll
            for (int m = 0; m < 5; m++) {
                gemm_gate((m == 0) ? hT : (xb + (m - 1) * 2176), Bs + (m & 1) * 8192, acc, nl, cg);
                if (m < 4) {
                    float4* d = (float4*)(Bs + ((m + 1) & 1) * 8192);
                    d[tid] = pf0; d[tid + 512] = pf1; d[tid + 1024] = pf2; d[tid + 1536] = pf3;
                    if (m < 3) {
                        pf0 = Wg4[(m + 2) * 2048 + tid];        pf1 = Wg4[(m + 2) * 2048 + tid + 512];
                        pf2 = Wg4[(m + 2) * 2048 + tid + 1024]; pf3 = Wg4[(m + 2) * 2048 + tid + 1536];
                    }
                    __syncthreads();
                }
            }
            float gx[8] = {gx0.x, gx0.y, gx0.z, gx0.w, gx1.x, gx1.y, gx1.z, gx1.w};
            if (cg < 8) {
                float rv[8];
#pragma unroll
                for (int j = 0; j < 4; j++) {
                    int o = cg * 8 + 2 * j;
                    float lo, hi; upk2(acc[j], lo, hi);
                    float h0 = hT[o * 34 + nl], h1 = hT[(o + 1) * 34 + nl];
                    float r0 = sigm(lo + gx[2 * j]) * h0;
                    float r1 = sigm(hi + gx[2 * j + 1]) * h1;
                    rhN[ng * 68 + o] = r0; rhN[ng * 68 + o + 1] = r1;
                    rhT[o * 34 + nl] = r0; rhT[(o + 1) * 34 + nl] = r1;
                    rv[2 * j] = r0; rv[2 * j + 1] = r1;
                }
                st_rem_v4(rhN_rem + cg * 32, make_float4(rv[0], rv[1], rv[2], rv[3]));
                st_rem_v4(rhN_rem + cg * 32 + 16, make_float4(rv[4], rv[5], rv[6], rv[7]));
            } else {
#pragma unroll
                for (int j = 0; j < 4; j++) {
                    int o = cg * 8 + 2 * j;
                    float lo, hi; upk2(acc[j], lo, hi);
                    uT[(o - 64) * 34 + nl] = sigm(lo + gx[2 * j]);
                    uT[(o - 63) * 34 + nl] = sigm(hi + gx[2 * j + 1]);
                }
            }
        }
        CLUSTER_SYNC();

        // ===== CAND =====
        {
            const float* CxP = g_Cx + (((size_t)t * Bn + b) * 64 + ng) * 64 + cg * 4;
            float4 cx = __ldg((const float4*)CxP);
            ull acc[2] = {0, 0};
            float4 pc0 = Wc4[tid], pc1 = Wc4[tid + 512];
            ((float4*)Bs)[tid] = pc0; ((float4*)Bs)[tid + 512] = pc1;
            pc0 = Wc4[1024 + tid]; pc1 = Wc4[1024 + tid + 512];
            diff1(rhN, sPh, xb, cg, nl);
            __syncthreads();
#pragma unroll
            for (int m = 0; m < 5; m++) {
                gemm_cand((m == 0) ? rhT : (xb + (m - 1) * 2176), Bs + (m & 1) * 8192, acc, nl, cg);
                if (m < 4) {
                    float4* d = (float4*)(Bs + ((m + 1) & 1) * 8192);
                    d[tid] = pc0; d[tid + 512] = pc1;
                    if (m < 3) {
                        pc0 = Wc4[(m + 2) * 1024 + tid];
                        pc1 = Wc4[(m + 2) * 1024 + tid + 512];
                    }
                    __syncthreads();
                }
            }
            float cxv[4] = {cx.x, cx.y, cx.z, cx.w};
            float hv[4];
            bool isLast = (LAYER == 1) && (t == last_t);
#pragma unroll
            for (int j = 0; j < 2; j++) {
                int o = cg * 4 + 2 * j;
                float lo, hi; upk2(acc[j], lo, hi);
                float c0 = tanhfast(lo + cxv[2 * j]);
                float c1 = tanhfast(hi + cxv[2 * j + 1]);
                float u0 = uT[o * 34 + nl], u1 = uT[(o + 1) * 34 + nl];
                float h0 = hT[o * 34 + nl], h1 = hT[(o + 1) * 34 + nl];
                hv[2 * j] = u0 * h0 + (1.f - u0) * c0;
                hv[2 * j + 1] = u1 * h1 + (1.f - u1) * c1;
            }
#pragma unroll
            for (int j = 0; j < 2; j++) {
                int o = cg * 4 + 2 * j;
                hN[ng * 68 + o] = hv[2 * j]; hN[ng * 68 + o + 1] = hv[2 * j + 1];
                hT[o * 34 + nl] = hv[2 * j]; hT[(o + 1) * 34 + nl] = hv[2 * j + 1];
            }
            float4 hq = make_float4(hv[0], hv[1], hv[2], hv[3]);
            st_rem_v4(hN_rem + cg * 16, hq);
            if (LAYER == 0)
                *(float4*)(g_Hseq + ((size_t)t * Bn + b) * 4096 + ng * 64 + cg * 4) = hq;
            if (isLast)
                *(float4*)(g_Last + (size_t)(b * 64 + ng) * 64 + cg * 4) = hq;
        }
        CLUSTER_SYNC();
        if (PUBLISH && tid == 0) flag_release(&g_prog[b * 2 + hf]);
    }
}

// ---------- fused: recur0 + pre1 + recur1 ----------
__global__ void __launch_bounds__(512, 1) __cluster_dims__(2, 1, 1)
k_fused(const float* __restrict__ bg1, const float* __restrict__ bc1,
        const int* __restrict__ seql) {
    const int PRE_Y = Bn + (Tn * Bn) / 2;
    if (blockIdx.y < Bn) {
        recur_body<0, true, false>(blockIdx.y, seql);
    } else if (blockIdx.y < PRE_Y) {
        int p = (blockIdx.y - Bn) * 2 + blockIdx.x;
        int t = p / Bn, b = p % Bn;
        if (t >= seql[b]) return;
        if (threadIdx.x == 0) {
            const int* p0 = &g_prog[b * 2];
            const int* p1 = &g_prog[b * 2 + 1];
            while (flag_acq(p0) <= t) __nanosleep(256);
            while (flag_acq(p1) <= t) __nanosleep(256);
        }
        __syncthreads();
        pre_body(1, t, b, nullptr, bg1, bc1);
        __syncthreads();
        if (threadIdx.x == 0) flag_release(&g_prog1[t * Bn + b]);
    } else {
        recur_body<1, false, true>(blockIdx.y - PRE_Y, seql);
    }
}

// ---------- output head ----------
__global__ void k_head(const float* __restrict__ fcw, const float* __restrict__ fcb,
                       const float* __restrict__ idw, const float* __restrict__ idb,
                       float* __restrict__ out) {
    __shared__ float hb[4096];
    __shared__ float w[64 * 54];
    __shared__ float bias[54];
    int b = blockIdx.x, tid = threadIdx.x;
    for (int i = tid; i < 4096; i += 256) hb[i] = fmaxf(g_Last[b * 4096 + i], 0.f);
    for (int i = tid; i < 64 * 54; i += 256) {
        int k = i / 54, c = i % 54;
        w[i] = (c < 4) ? fcw[k * 4 + c] : idw[k * 50 + c - 4];
    }
    if (tid < 54) bias[tid] = (tid < 4) ? fcb[tid] : idb[tid - 4];
    __syncthreads();
    if (tid < 54) {
        float best = -INFINITY;
        for (int nn = 0; nn < 64; nn++) {
            float s = bias[tid];
            for (int k = 0; k < 64; k++) s += hb[nn * 64 + k] * w[k * 54 + tid];
            best = fmaxf(best, s);
        }
        if (tid < 4) out[b * 4 + tid] = best;
        else out[256 + b * 50 + tid - 4] = best;
    }
}

extern "C" void kernel_launch(void* const* d_in, const int* in_sizes, int n_in,
                              void* d_out, int out_size) {
    const float* xseq = (const float*)d_in[0];
    const int* seql = (const int*)d_in[1];
    const float* S0 = (const float*)d_in[2];
    const float* S1 = (const float*)d_in[3];
    const float* Wg0 = (const float*)d_in[4]; const float* bg0 = (const float*)d_in[5];
    const float* Wc0 = (const float*)d_in[6]; const float* bc0 = (const float*)d_in[7];
    const float* Wg1 = (const float*)d_in[8]; const float* bg1 = (const float*)d_in[9];
    const float* Wc1 = (const float*)d_in[10]; const float* bc1 = (const float*)d_in[11];
    const float* fcw = (const float*)d_in[12]; const float* fcb = (const float*)d_in[13];
    const float* idw = (const float*)d_in[14]; const float* idb = (const float*)d_in[15];
    float* out = (float*)d_out;

    const int SM_PRE0 = 24832 * 4;                                  // 99328 (2 CTAs/SM)
    const int SM_FUSED = (4224 + 4352 + 16896 + 12288 + 16384) * 4; // 216576
    cudaFuncSetAttribute(k_pre0, cudaFuncAttributeMaxDynamicSharedMemorySize, SM_PRE0);
    cudaFuncSetAttribute(k_fused, cudaFuncAttributeMaxDynamicSharedMemorySize, SM_FUSED);

    k_prep<<<1, 256>>>(S0, S1);
    k_pack<<<240, 256>>>(Wg0, Wc0, Wg1, Wc1);

    k_pre0<<<dim3(Tn, Bn), 512, SM_PRE0>>>(xseq, bg0, bc0, seql);
    k_fused<<<dim3(2, Bn + (Tn * Bn) / 2 + Bn), 512, SM_FUSED>>>(bg1, bc1, seql);

    k_head<<<Bn, 256>>>(fcw, fcb, idw, idb, out);
}